// round 8
// baseline (speedup 1.0000x reference)
#include <cuda_runtime.h>
#include <math.h>
#include <stdint.h>

// ---------------- static config ----------------
#define TOK   100352          // 32 * 56 * 56 tokens
#define SCALE 0.17677669529663687f   // 32^-0.5

// ---------------- scratch (device globals; no allocs allowed) ----------------
__device__ float g_a[TOK * 256];      // LN1-window output; reused for attention output
__device__ float g_qkv[TOK * 768];    // QKV; reused for LN2 output
__device__ float g_h[TOK * 1024];     // FC1/GELU output
// transposed + tf32-rounded weights
__device__ float g_wT[196608 + 65536 + 262144 + 262144];
#define OFF_QKVT 0
#define OFF_PROJT 196608
#define OFF_FC1T 262144
#define OFF_FC2T 524288

// ---------------- helpers ----------------
__device__ __forceinline__ float tf32r(float x)
{
    uint32_t u;
    asm("cvt.rna.tf32.f32 %0, %1;" : "=r"(u) : "f"(x));
    return __uint_as_float(u);
}

__device__ __forceinline__ float gelu_exact(float x)
{
    return 0.5f * x * (1.0f + erff(x * 0.70710678118654752f));
}

__device__ __forceinline__ int unshift_row(int mr)
{
    int ntok = mr % 49; int wb = mr / 49;
    int wwi = wb & 7, wh = (wb >> 3) & 7, b = wb >> 6;
    int r = ntok / 7, c = ntok % 7;
    int oh = wh * 7 + r + 3; if (oh >= 56) oh -= 56;
    int ow = wwi * 7 + c + 3; if (ow >= 56) ow -= 56;
    return b * 3136 + oh * 56 + ow;
}

__device__ __forceinline__ void cpa16(uint32_t dst, const void* src)
{
    asm volatile("cp.async.cg.shared.global [%0], [%1], 16;" :: "r"(dst), "l"(src));
}

__device__ __forceinline__ void ldsm4(uint32_t addr, uint32_t& r0, uint32_t& r1,
                                      uint32_t& r2, uint32_t& r3)
{
    asm volatile("ldmatrix.sync.aligned.m8n8.x4.shared.b16 {%0,%1,%2,%3}, [%4];"
                 : "=r"(r0), "=r"(r1), "=r"(r2), "=r"(r3) : "r"(addr));
}

// ---------------- weight transpose + tf32 round: in[K][N] -> out[N][K] ----------------
__global__ void transpose_tf32(const float* __restrict__ in, float* __restrict__ out,
                               int K, int N)
{
    __shared__ float t[32][33];
    int bx = blockIdx.x * 32;   // n
    int by = blockIdx.y * 32;   // k
    int tx = threadIdx.x, ty = threadIdx.y;
#pragma unroll
    for (int i = 0; i < 32; i += 8)
        t[ty + i][tx] = in[(size_t)(by + ty + i) * N + bx + tx];
    __syncthreads();
#pragma unroll
    for (int i = 0; i < 32; i += 8)
        out[(size_t)(bx + ty + i) * K + by + tx] = tf32r(t[tx][ty + i]);
}

// ---------------- LayerNorm (optionally fused with shift+window gather) ----------------
template<bool WIN>
__global__ void ln_kernel(const float* __restrict__ in, const float* __restrict__ gm,
                          const float* __restrict__ bt, float* __restrict__ out)
{
    int gw   = (blockIdx.x * blockDim.x + threadIdx.x) >> 5;
    int lane = threadIdx.x & 31;
    if (gw >= TOK) return;

    const float* src;
    if (WIN) src = in + (size_t)unshift_row(gw) * 256;
    else     src = in + (size_t)gw * 256;

    float v[8];
#pragma unroll
    for (int i = 0; i < 8; i++) v[i] = src[lane + 32 * i];

    float s = 0.f;
#pragma unroll
    for (int i = 0; i < 8; i++) s += v[i];
#pragma unroll
    for (int o = 16; o > 0; o >>= 1) s += __shfl_xor_sync(0xffffffffu, s, o);
    float mean = s * (1.0f / 256.0f);

    float q = 0.f;
#pragma unroll
    for (int i = 0; i < 8; i++) { float d = v[i] - mean; q += d * d; }
#pragma unroll
    for (int o = 16; o > 0; o >>= 1) q += __shfl_xor_sync(0xffffffffu, q, o);
    float rstd = rsqrtf(q * (1.0f / 256.0f) + 1e-5f);

    float* orow = out + (size_t)gw * 256;
#pragma unroll
    for (int i = 0; i < 8; i++) {
        int cc = lane + 32 * i;
        orow[cc] = tf32r((v[i] - mean) * rstd * gm[cc] + bt[cc]);
    }
}

// ---------------- tf32 tensor-core GEMM ----------------
// C[M,NN] = A[M,K] @ BT^T + epilogue   (BT is [NN][K], tf32-rounded)
// MODE 0: out = acc + bias                                  (QKV)
// MODE 1: out[dst] = res[dst] + acc + bias, dst = unshift   (proj + scatter + residual)
// MODE 2: out = tf32r(gelu(acc + bias))                     (FC1)
// MODE 3: out = res + acc + bias                            (FC2 + residual)
//
// block 256x128, BK=32, 8 warps (4x2), warp tile 64x64, mma m16n8k8 tf32.
// smem: 2 stages x (A 32KB + B 16KB) = 96KB, 128B rows, XOR swizzle,
// cp.async staging, ldmatrix.x4 fragments for A and B.
template<int K, int NN, int MODE>
__global__ __launch_bounds__(256, 2) void mma_gemm(
    const float* __restrict__ A, const float* __restrict__ BT,
    const float* __restrict__ bias, float* __restrict__ out,
    const float* __restrict__ res)
{
    extern __shared__ float smdyn[];
    const int tid  = threadIdx.x;
    const int lane = tid & 31;
    const int warp = tid >> 5;
    const int wm = warp >> 1, wn = warp & 1;     // 4 x 2 warp grid
    const int bm = blockIdx.y, bn = blockIdx.x;

    const uint32_t sbase = (uint32_t)__cvta_generic_to_shared(smdyn);
    // A stage s at sbase + s*32768 ; B stage s at sbase + 65536 + s*16384

    // staging: 32 rows x 8 granules per pass; A 8 passes (256 rows), B 4 passes (128 rows)
    const int lr = tid >> 3;   // 0..31
    const int lg = tid & 7;    // 0..7
    const uint32_t swz = (uint32_t)((lg ^ (lr & 7)) << 4);
    const float* Ag = A  + (size_t)(bm * 256 + lr) * K + lg * 4;
    const float* Bg = BT + (size_t)(bn * 128 + lr) * K + lg * 4;
    const uint32_t dA = sbase + lr * 128 + swz;
    const uint32_t dB = sbase + 65536 + lr * 128 + swz;

    float c[4][8][4];
#pragma unroll
    for (int i = 0; i < 4; i++)
#pragma unroll
        for (int j = 0; j < 8; j++)
#pragma unroll
            for (int l = 0; l < 4; l++) c[i][j][l] = 0.f;

    auto stage_fn = [&](int kt, int s) {
        const float* a = Ag + kt * 32;
        const float* b = Bg + kt * 32;
        const uint32_t oa = (uint32_t)(s * 32768);
        const uint32_t ob = (uint32_t)(s * 16384);
#pragma unroll
        for (int i = 0; i < 8; i++)
            cpa16(dA + oa + i * 4096, a + (size_t)i * 32 * K);
#pragma unroll
        for (int i = 0; i < 4; i++)
            cpa16(dB + ob + i * 4096, b + (size_t)i * 32 * K);
        asm volatile("cp.async.commit_group;");
    };

    stage_fn(0, 0);
    asm volatile("cp.async.wait_group 0;");
    __syncthreads();

    // ldmatrix row bases (row&7 == lane&7 for all fragment rows)
    const int l15 = lane & 15, hi = lane >> 4, l7 = lane & 7;
    uint32_t aRow[4], bRow[4];
#pragma unroll
    for (int mi = 0; mi < 4; mi++)
        aRow[mi] = sbase + (uint32_t)((wm * 64 + mi * 16 + l15) * 128);
#pragma unroll
    for (int j = 0; j < 4; j++)
        bRow[j] = sbase + 65536 + (uint32_t)((wn * 64 + j * 16 + l15) * 128);

    const int KT = K / 32;
    int buf = 0;
#pragma unroll 1
    for (int kt = 0; kt < KT; kt++) {
        if (kt + 1 < KT) stage_fn(kt + 1, buf ^ 1);
        const uint32_t aoff = (uint32_t)(buf * 32768);
        const uint32_t boff2 = (uint32_t)(buf * 16384);
#pragma unroll
        for (int ks = 0; ks < 4; ks++) {
            const uint32_t gph = (uint32_t)(((2 * ks + hi) ^ l7) << 4);
            uint32_t af[4][4], bq[4][4];
#pragma unroll
            for (int mi = 0; mi < 4; mi++)
                ldsm4(aRow[mi] + gph + aoff, af[mi][0], af[mi][1], af[mi][2], af[mi][3]);
#pragma unroll
            for (int j = 0; j < 4; j++)
                ldsm4(bRow[j] + gph + boff2, bq[j][0], bq[j][1], bq[j][2], bq[j][3]);
#pragma unroll
            for (int mi = 0; mi < 4; mi++)
#pragma unroll
                for (int ni = 0; ni < 8; ni++) {
                    asm volatile(
                        "mma.sync.aligned.m16n8k8.row.col.f32.tf32.tf32.f32 "
                        "{%0,%1,%2,%3}, {%4,%5,%6,%7}, {%8,%9}, {%0,%1,%2,%3};"
                        : "+f"(c[mi][ni][0]), "+f"(c[mi][ni][1]),
                          "+f"(c[mi][ni][2]), "+f"(c[mi][ni][3])
                        : "r"(af[mi][0]), "r"(af[mi][1]),
                          "r"(af[mi][2]), "r"(af[mi][3]),
                          "r"(bq[ni >> 1][ni & 1]), "r"(bq[ni >> 1][2 + (ni & 1)]));
                }
        }
        if (kt + 1 < KT) {
            asm volatile("cp.async.wait_group 0;");
            __syncthreads();
            buf ^= 1;
        }
    }

    // ---- epilogue ----
#pragma unroll
    for (int mi = 0; mi < 4; mi++) {
        int mr0 = bm * 256 + wm * 64 + mi * 16 + (lane >> 2);
        int mr1 = mr0 + 8;
        size_t dst0, dst1;
        if (MODE == 1) { dst0 = (size_t)unshift_row(mr0); dst1 = (size_t)unshift_row(mr1); }
        else           { dst0 = (size_t)mr0;              dst1 = (size_t)mr1; }
#pragma unroll
        for (int ni = 0; ni < 8; ni++) {
            int col = bn * 128 + wn * 64 + ni * 8 + 2 * (lane & 3);
            float2 bb = *(const float2*)&bias[col];
            float2 o0, o1;
            o0.x = c[mi][ni][0] + bb.x; o0.y = c[mi][ni][1] + bb.y;
            o1.x = c[mi][ni][2] + bb.x; o1.y = c[mi][ni][3] + bb.y;
            if (MODE == 1 || MODE == 3) {
                float2 r0v = *(const float2*)&res[dst0 * NN + col];
                float2 r1v = *(const float2*)&res[dst1 * NN + col];
                o0.x += r0v.x; o0.y += r0v.y;
                o1.x += r1v.x; o1.y += r1v.y;
            }
            if (MODE == 2) {
                o0.x = tf32r(gelu_exact(o0.x)); o0.y = tf32r(gelu_exact(o0.y));
                o1.x = tf32r(gelu_exact(o1.x)); o1.y = tf32r(gelu_exact(o1.y));
            }
            *(float2*)&out[dst0 * NN + col] = o0;
            *(float2*)&out[dst1 * NN + col] = o1;
        }
    }
}

// ---------------- windowed attention (register-blocked) ----------------
__global__ __launch_bounds__(256) void attn_kernel(const float* __restrict__ qkv,
                                                   const float* __restrict__ rpb,
                                                   float* __restrict__ out)
{
    const int wb = blockIdx.x;   // 0..2047
    const int h  = blockIdx.y;   // 0..7
    const int tid = threadIdx.x;

    __shared__ float qs[50 * 36];
    __shared__ float ks[50 * 36];
    __shared__ float vs[49 * 36];
    __shared__ float sc[49 * 49];
    __shared__ float rpb_s[169];
    __shared__ int   lab[49];

    for (int idx = tid; idx < 49 * 32; idx += 256) {
        int n = idx >> 5, d = idx & 31;
        size_t base = (size_t)(wb * 49 + n) * 768 + h * 32 + d;
        qs[n * 36 + d] = qkv[base] * SCALE;
        ks[n * 36 + d] = qkv[base + 256];
        vs[n * 36 + d] = qkv[base + 512];
    }
    if (tid < 32) { qs[49 * 36 + tid] = 0.f; ks[49 * 36 + tid] = 0.f; }
    for (int i = tid; i < 169; i += 256) rpb_s[i] = rpb[i * 8 + h];
    if (tid < 49) {
        int wwi = wb & 7, wh = (wb >> 3) & 7;
        int r = tid / 7, c = tid % 7;
        int gr = wh * 7 + r, gc = wwi * 7 + c;
        int lr = gr < 49 ? 0 : (gr < 53 ? 1 : 2);
        int lc = gc < 49 ? 0 : (gc < 53 ? 1 : 2);
        lab[tid] = lr * 3 + lc;
    }
    __syncthreads();

    auto finish = [&](int i, int j, float s) {
        int ri = i / 7, ci = i % 7, rj = j / 7, cj = j % 7;
        s += rpb_s[(ri - rj + 6) * 13 + (ci - cj + 6)];
        if (lab[i] != lab[j]) s -= 100.0f;
        sc[i * 49 + j] = s;
    };
    for (int t = tid; t < 625; t += 256) {
        int ti = t / 25, tj = t % 25;
        int i0 = ti * 2, j0 = tj * 2;
        float s00 = 0.f, s01 = 0.f, s10 = 0.f, s11 = 0.f;
        const float* q0 = &qs[i0 * 36];
        const float* q1 = q0 + 36;
        const float* k0 = &ks[j0 * 36];
        const float* k1 = k0 + 36;
#pragma unroll
        for (int d = 0; d < 32; d += 4) {
            float4 a0 = *(const float4*)(q0 + d);
            float4 a1 = *(const float4*)(q1 + d);
            float4 b0 = *(const float4*)(k0 + d);
            float4 b1 = *(const float4*)(k1 + d);
            s00 += a0.x * b0.x + a0.y * b0.y + a0.z * b0.z + a0.w * b0.w;
            s01 += a0.x * b1.x + a0.y * b1.y + a0.z * b1.z + a0.w * b1.w;
            s10 += a1.x * b0.x + a1.y * b0.y + a1.z * b0.z + a1.w * b0.w;
            s11 += a1.x * b1.x + a1.y * b1.y + a1.z * b1.z + a1.w * b1.w;
        }
        bool iv = (i0 + 1 < 49), jv = (j0 + 1 < 49);
        finish(i0, j0, s00);
        if (jv) finish(i0, j0 + 1, s01);
        if (iv) finish(i0 + 1, j0, s10);
        if (iv && jv) finish(i0 + 1, j0 + 1, s11);
    }
    __syncthreads();

    {
        int warp = tid >> 5, lane = tid & 31;
        for (int r = warp; r < 49; r += 8) {
            float v0 = sc[r * 49 + lane];
            float v1 = (lane + 32 < 49) ? sc[r * 49 + lane + 32] : -1e30f;
            float mx = fmaxf(v0, v1);
#pragma unroll
            for (int o = 16; o > 0; o >>= 1) mx = fmaxf(mx, __shfl_xor_sync(0xffffffffu, mx, o));
            float e0 = __expf(v0 - mx);
            float e1 = (lane + 32 < 49) ? __expf(v1 - mx) : 0.f;
            float sum = e0 + e1;
#pragma unroll
            for (int o = 16; o > 0; o >>= 1) sum += __shfl_xor_sync(0xffffffffu, sum, o);
            float inv = 1.0f / sum;
            sc[r * 49 + lane] = e0 * inv;
            if (lane + 32 < 49) sc[r * 49 + lane + 32] = e1 * inv;
        }
    }
    __syncthreads();

    for (int t = tid; t < 49 * 8; t += 256) {
        int i = t >> 3, dq = (t & 7) * 4;
        const float* sr = &sc[i * 49];
        float4 acc = make_float4(0.f, 0.f, 0.f, 0.f);
#pragma unroll 7
        for (int j = 0; j < 49; j++) {
            float p = sr[j];
            float4 v = *(const float4*)&vs[j * 36 + dq];
            acc.x += p * v.x; acc.y += p * v.y; acc.z += p * v.z; acc.w += p * v.w;
        }
        float4 o;
        o.x = tf32r(acc.x); o.y = tf32r(acc.y); o.z = tf32r(acc.z); o.w = tf32r(acc.w);
        *(float4*)&out[(size_t)(wb * 49 + i) * 256 + h * 32 + dq] = o;
    }
}

// ---------------- launch ----------------
extern "C" void kernel_launch(void* const* d_in, const int* in_sizes, int n_in,
                              void* d_out, int out_size)
{
    const float* x      = (const float*)d_in[0];
    const float* gamma1 = (const float*)d_in[1];
    const float* beta1  = (const float*)d_in[2];
    const float* qkv_w  = (const float*)d_in[3];
    const float* qkv_b  = (const float*)d_in[4];
    const float* proj_w = (const float*)d_in[5];
    const float* proj_b = (const float*)d_in[6];
    const float* rpb    = (const float*)d_in[7];
    const float* gamma2 = (const float*)d_in[8];
    const float* beta2  = (const float*)d_in[9];
    const float* fc1_w  = (const float*)d_in[10];
    const float* fc1_b  = (const float*)d_in[11];
    const float* fc2_w  = (const float*)d_in[12];
    const float* fc2_b  = (const float*)d_in[13];
    float* out = (float*)d_out;

    float *pa, *pqkv, *ph, *pw;
    cudaGetSymbolAddress((void**)&pa, g_a);
    cudaGetSymbolAddress((void**)&pqkv, g_qkv);
    cudaGetSymbolAddress((void**)&ph, g_h);
    cudaGetSymbolAddress((void**)&pw, g_wT);

    const int DSMEM = 98304;   // 2 stages x (32KB A + 16KB B)
    cudaFuncSetAttribute(mma_gemm<256, 768, 0>, cudaFuncAttributeMaxDynamicSharedMemorySize, DSMEM);
    cudaFuncSetAttribute(mma_gemm<256, 256, 1>, cudaFuncAttributeMaxDynamicSharedMemorySize, DSMEM);
    cudaFuncSetAttribute(mma_gemm<256, 1024, 2>, cudaFuncAttributeMaxDynamicSharedMemorySize, DSMEM);
    cudaFuncSetAttribute(mma_gemm<1024, 256, 3>, cudaFuncAttributeMaxDynamicSharedMemorySize, DSMEM);

    // 0. transpose + tf32-round weights
    transpose_tf32<<<dim3(768 / 32, 256 / 32), dim3(32, 8)>>>(qkv_w, pw + OFF_QKVT, 256, 768);
    transpose_tf32<<<dim3(256 / 32, 256 / 32), dim3(32, 8)>>>(proj_w, pw + OFF_PROJT, 256, 256);
    transpose_tf32<<<dim3(1024 / 32, 256 / 32), dim3(32, 8)>>>(fc1_w, pw + OFF_FC1T, 256, 1024);
    transpose_tf32<<<dim3(256 / 32, 1024 / 32), dim3(32, 8)>>>(fc2_w, pw + OFF_FC2T, 1024, 256);

    // 1. LN1 + cyclic shift + window partition -> g_a
    ln_kernel<true><<<TOK / 8, 256>>>(x, gamma1, beta1, pa);
    // 2. QKV GEMM -> g_qkv   (M tiles of 256: 100352/256 = 392)
    mma_gemm<256, 768, 0><<<dim3(6, 392), 256, DSMEM>>>(pa, pw + OFF_QKVT, qkv_b, pqkv, nullptr);
    // 3. attention -> g_a (reused)
    attn_kernel<<<dim3(2048, 8), 256>>>(pqkv, rpb, pa);
    // 4. proj GEMM + window reverse + roll scatter + residual -> d_out
    mma_gemm<256, 256, 1><<<dim3(2, 392), 256, DSMEM>>>(pa, pw + OFF_PROJT, proj_b, out, x);
    // 5. LN2 -> g_qkv (reused)
    ln_kernel<false><<<TOK / 8, 256>>>(out, gamma2, beta2, pqkv);
    // 6. FC1 + GELU -> g_h
    mma_gemm<256, 1024, 2><<<dim3(8, 392), 256, DSMEM>>>(pqkv, pw + OFF_FC1T, fc1_b, ph, nullptr);
    // 7. FC2 + residual -> d_out
    mma_gemm<1024, 256, 3><<<dim3(2, 392), 256, DSMEM>>>(ph, pw + OFF_FC2T, fc2_b, out, out);
    (void)in_sizes; (void)n_in; (void)out_size;
}

// round 9
// speedup vs baseline: 2.2884x; 2.2884x over previous
#include <cuda_runtime.h>
#include <math.h>
#include <stdint.h>

// ---------------- static config ----------------
#define TOK   100352          // 32 * 56 * 56 tokens
#define SCALE 0.17677669529663687f   // 32^-0.5

// ---------------- scratch (device globals; no allocs allowed) ----------------
__device__ float g_a[TOK * 256];      // LN1-window output; reused for attention output
__device__ float g_qkv[TOK * 768];    // QKV; reused for LN2 output
__device__ float g_h[TOK * 1024];     // FC1/GELU output
// transposed + tf32-rounded weights
__device__ float g_wT[196608 + 65536 + 262144 + 262144];
#define OFF_QKVT 0
#define OFF_PROJT 196608
#define OFF_FC1T 262144
#define OFF_FC2T 524288

// ---------------- helpers ----------------
__device__ __forceinline__ float tf32r(float x)
{
    uint32_t u;
    asm("cvt.rna.tf32.f32 %0, %1;" : "=r"(u) : "f"(x));
    return __uint_as_float(u);
}

__device__ __forceinline__ float gelu_exact(float x)
{
    return 0.5f * x * (1.0f + erff(x * 0.70710678118654752f));
}

// unshifted destination row for window-layout row mr (window reverse + roll)
__device__ __forceinline__ int unshift_row(int mr)
{
    int ntok = mr % 49; int wb = mr / 49;
    int wwi = wb & 7, wh = (wb >> 3) & 7, b = wb >> 6;
    int r = ntok / 7, c = ntok % 7;
    int oh = wh * 7 + r + 3; if (oh >= 56) oh -= 56;
    int ow = wwi * 7 + c + 3; if (ow >= 56) ow -= 56;
    return b * 3136 + oh * 56 + ow;
}

__device__ __forceinline__ void cpa16(uint32_t dst, const void* src)
{
    asm volatile("cp.async.cg.shared.global [%0], [%1], 16;" :: "r"(dst), "l"(src));
}

__device__ __forceinline__ void ldsm4(uint32_t addr, uint32_t& r0, uint32_t& r1,
                                      uint32_t& r2, uint32_t& r3)
{
    asm volatile("ldmatrix.sync.aligned.m8n8.x4.shared.b16 {%0,%1,%2,%3}, [%4];"
                 : "=r"(r0), "=r"(r1), "=r"(r2), "=r"(r3) : "r"(addr));
}

// ---------------- weight transpose + tf32 round: in[K][N] -> out[N][K] ----------------
__global__ void transpose_tf32(const float* __restrict__ in, float* __restrict__ out,
                               int K, int N)
{
    __shared__ float t[32][33];
    int bx = blockIdx.x * 32;   // n
    int by = blockIdx.y * 32;   // k
    int tx = threadIdx.x, ty = threadIdx.y;
#pragma unroll
    for (int i = 0; i < 32; i += 8)
        t[ty + i][tx] = in[(size_t)(by + ty + i) * N + bx + tx];
    __syncthreads();
#pragma unroll
    for (int i = 0; i < 32; i += 8)
        out[(size_t)(bx + ty + i) * K + by + tx] = tf32r(t[tx][ty + i]);
}

// ---------------- LayerNorm (optionally fused with shift+window gather) ----------------
template<bool WIN>
__global__ void ln_kernel(const float* __restrict__ in, const float* __restrict__ gm,
                          const float* __restrict__ bt, float* __restrict__ out)
{
    int gw   = (blockIdx.x * blockDim.x + threadIdx.x) >> 5;
    int lane = threadIdx.x & 31;
    if (gw >= TOK) return;

    const float* src;
    if (WIN) src = in + (size_t)unshift_row(gw) * 256;
    else     src = in + (size_t)gw * 256;

    float v[8];
#pragma unroll
    for (int i = 0; i < 8; i++) v[i] = src[lane + 32 * i];

    float s = 0.f;
#pragma unroll
    for (int i = 0; i < 8; i++) s += v[i];
#pragma unroll
    for (int o = 16; o > 0; o >>= 1) s += __shfl_xor_sync(0xffffffffu, s, o);
    float mean = s * (1.0f / 256.0f);

    float q = 0.f;
#pragma unroll
    for (int i = 0; i < 8; i++) { float d = v[i] - mean; q += d * d; }
#pragma unroll
    for (int o = 16; o > 0; o >>= 1) q += __shfl_xor_sync(0xffffffffu, q, o);
    float rstd = rsqrtf(q * (1.0f / 256.0f) + 1e-5f);

    float* orow = out + (size_t)gw * 256;
#pragma unroll
    for (int i = 0; i < 8; i++) {
        int cc = lane + 32 * i;
        orow[cc] = tf32r((v[i] - mean) * rstd * gm[cc] + bt[cc]);
    }
}

// ---------------- tf32 tensor-core GEMM (round-4 proven config) ----------------
// C[M,NN] = A[M,K] @ BT^T + epilogue   (BT is [NN][K], tf32-rounded)
// MODE 0: out = acc + bias                                  (QKV)
// MODE 1: out[dst] = res[dst] + acc + bias, dst = unshift   (proj + scatter + residual)
// MODE 2: out = tf32r(gelu(acc + bias))                     (FC1)
// MODE 3: out = res + acc + bias                            (FC2 + residual)
//
// block 128x128, BK=32, 4 warps (2x2), warp tile 64x64, mma m16n8k8 tf32.
// smem: 2 stages x (A 16KB + B 16KB) = 64KB -> 3 CTAs/SM; XOR swizzle,
// cp.async staging, ldmatrix.x4 fragments for A and B.
template<int K, int NN, int MODE>
__global__ __launch_bounds__(128) void mma_gemm(
    const float* __restrict__ A, const float* __restrict__ BT,
    const float* __restrict__ bias, float* __restrict__ out,
    const float* __restrict__ res)
{
    extern __shared__ float smdyn[];
    const int tid  = threadIdx.x;
    const int lane = tid & 31;
    const int warp = tid >> 5;
    const int wm = warp >> 1, wn = warp & 1;
    const int bm = blockIdx.y, bn = blockIdx.x;

    const uint32_t sbase = (uint32_t)__cvta_generic_to_shared(smdyn);
    const uint32_t sA0 = sbase;            // 2 buffers x 16KB
    const uint32_t sB0 = sbase + 32768;    // 2 buffers x 16KB

    // staging thread mapping: 16 rows x 8 granules, 8 row-steps of 16
    const int lr = tid >> 3;   // 0..15
    const int lg = tid & 7;    // 0..7
    const uint32_t swz = (uint32_t)((lg ^ (lr & 7)) << 4);
    const float* Ag = A  + (size_t)(bm * 128 + lr) * K + lg * 4;
    const float* Bg = BT + (size_t)(bn * 128 + lr) * K + lg * 4;
    const uint32_t dA = sA0 + lr * 128 + swz;
    const uint32_t dB = sB0 + lr * 128 + swz;

    float c[4][8][4];
#pragma unroll
    for (int i = 0; i < 4; i++)
#pragma unroll
        for (int j = 0; j < 8; j++)
#pragma unroll
            for (int l = 0; l < 4; l++) c[i][j][l] = 0.f;

#define PREF(KT, BUF)                                                     \
    do {                                                                  \
        const float* _a = Ag + (KT) * 32;                                 \
        const float* _b = Bg + (KT) * 32;                                 \
        uint32_t _o = (BUF) * 16384;                                      \
        _Pragma("unroll")                                                 \
        for (int i = 0; i < 8; i++) {                                     \
            cpa16(dA + _o + i * 2048, _a + (size_t)i * 16 * K);           \
            cpa16(dB + _o + i * 2048, _b + (size_t)i * 16 * K);           \
        }                                                                 \
        asm volatile("cp.async.commit_group;");                           \
    } while (0)

    PREF(0, 0);
    asm volatile("cp.async.wait_group 0;");
    __syncthreads();

    // ldmatrix row bases (row&7 == lane&7 for all fragment rows)
    const int l15 = lane & 15, hi = lane >> 4, l7 = lane & 7;
    uint32_t aRow[4], bRow[4];
#pragma unroll
    for (int mi = 0; mi < 4; mi++) aRow[mi] = sA0 + (uint32_t)((wm * 64 + mi * 16 + l15) * 128);
#pragma unroll
    for (int j = 0; j < 4; j++)    bRow[j]  = sB0 + (uint32_t)((wn * 64 + j * 16 + l15) * 128);

    int buf = 0;
    const int KT = K / 32;
#pragma unroll 1
    for (int kt = 0; kt < KT; kt++) {
        if (kt + 1 < KT) PREF(kt + 1, buf ^ 1);
        const uint32_t boff = (uint32_t)(buf * 16384);
#pragma unroll
        for (int ks = 0; ks < 4; ks++) {
            const uint32_t gph = (uint32_t)(((2 * ks + hi) ^ l7) << 4) + boff;
            uint32_t af[4][4], bq[4][4];
#pragma unroll
            for (int mi = 0; mi < 4; mi++)
                ldsm4(aRow[mi] + gph, af[mi][0], af[mi][1], af[mi][2], af[mi][3]);
#pragma unroll
            for (int j = 0; j < 4; j++)
                ldsm4(bRow[j] + gph, bq[j][0], bq[j][1], bq[j][2], bq[j][3]);
#pragma unroll
            for (int mi = 0; mi < 4; mi++)
#pragma unroll
                for (int ni = 0; ni < 8; ni++) {
                    asm volatile(
                        "mma.sync.aligned.m16n8k8.row.col.f32.tf32.tf32.f32 "
                        "{%0,%1,%2,%3}, {%4,%5,%6,%7}, {%8,%9}, {%0,%1,%2,%3};"
                        : "+f"(c[mi][ni][0]), "+f"(c[mi][ni][1]),
                          "+f"(c[mi][ni][2]), "+f"(c[mi][ni][3])
                        : "r"(af[mi][0]), "r"(af[mi][1]),
                          "r"(af[mi][2]), "r"(af[mi][3]),
                          "r"(bq[ni >> 1][ni & 1]), "r"(bq[ni >> 1][2 + (ni & 1)]));
                }
        }
        if (kt + 1 < KT) {
            asm volatile("cp.async.wait_group 0;");
            __syncthreads();
            buf ^= 1;
        }
    }
#undef PREF

    // ---- epilogue ----
#pragma unroll
    for (int mi = 0; mi < 4; mi++) {
        int mr0 = bm * 128 + wm * 64 + mi * 16 + (lane >> 2);
        int mr1 = mr0 + 8;
        size_t dst0, dst1;
        if (MODE == 1) { dst0 = (size_t)unshift_row(mr0); dst1 = (size_t)unshift_row(mr1); }
        else           { dst0 = (size_t)mr0;              dst1 = (size_t)mr1; }
#pragma unroll
        for (int ni = 0; ni < 8; ni++) {
            int col = bn * 128 + wn * 64 + ni * 8 + 2 * (lane & 3);
            float2 bb = *(const float2*)&bias[col];
            float2 o0, o1;
            o0.x = c[mi][ni][0] + bb.x; o0.y = c[mi][ni][1] + bb.y;
            o1.x = c[mi][ni][2] + bb.x; o1.y = c[mi][ni][3] + bb.y;
            if (MODE == 1 || MODE == 3) {
                float2 r0v = *(const float2*)&res[dst0 * NN + col];
                float2 r1v = *(const float2*)&res[dst1 * NN + col];
                o0.x += r0v.x; o0.y += r0v.y;
                o1.x += r1v.x; o1.y += r1v.y;
            }
            if (MODE == 2) {
                o0.x = tf32r(gelu_exact(o0.x)); o0.y = tf32r(gelu_exact(o0.y));
                o1.x = tf32r(gelu_exact(o1.x)); o1.y = tf32r(gelu_exact(o1.y));
            }
            *(float2*)&out[dst0 * NN + col] = o0;
            *(float2*)&out[dst1 * NN + col] = o1;
        }
    }
}

// ---------------- windowed attention (register-blocked, round-7 version) ----------------
__global__ __launch_bounds__(256) void attn_kernel(const float* __restrict__ qkv,
                                                   const float* __restrict__ rpb,
                                                   float* __restrict__ out)
{
    const int wb = blockIdx.x;   // 0..2047
    const int h  = blockIdx.y;   // 0..7
    const int tid = threadIdx.x;

    __shared__ float qs[50 * 36];   // stride 36 (float4-aligned), padded row 49
    __shared__ float ks[50 * 36];
    __shared__ float vs[49 * 36];
    __shared__ float sc[49 * 49];
    __shared__ float rpb_s[169];
    __shared__ int   lab[49];

    for (int idx = tid; idx < 49 * 32; idx += 256) {
        int n = idx >> 5, d = idx & 31;
        size_t base = (size_t)(wb * 49 + n) * 768 + h * 32 + d;
        qs[n * 36 + d] = qkv[base] * SCALE;
        ks[n * 36 + d] = qkv[base + 256];
        vs[n * 36 + d] = qkv[base + 512];
    }
    if (tid < 32) { qs[49 * 36 + tid] = 0.f; ks[49 * 36 + tid] = 0.f; }  // pad row
    for (int i = tid; i < 169; i += 256) rpb_s[i] = rpb[i * 8 + h];
    if (tid < 49) {
        int wwi = wb & 7, wh = (wb >> 3) & 7;
        int r = tid / 7, c = tid % 7;
        int gr = wh * 7 + r, gc = wwi * 7 + c;
        int lr = gr < 49 ? 0 : (gr < 53 ? 1 : 2);
        int lc = gc < 49 ? 0 : (gc < 53 ? 1 : 2);
        lab[tid] = lr * 3 + lc;
    }
    __syncthreads();

    // scores: 2x2 register tiles over a 25x25 tile grid
    auto finish = [&](int i, int j, float s) {
        int ri = i / 7, ci = i % 7, rj = j / 7, cj = j % 7;
        s += rpb_s[(ri - rj + 6) * 13 + (ci - cj + 6)];
        if (lab[i] != lab[j]) s -= 100.0f;
        sc[i * 49 + j] = s;
    };
    for (int t = tid; t < 625; t += 256) {
        int ti = t / 25, tj = t % 25;
        int i0 = ti * 2, j0 = tj * 2;
        float s00 = 0.f, s01 = 0.f, s10 = 0.f, s11 = 0.f;
        const float* q0 = &qs[i0 * 36];
        const float* q1 = q0 + 36;
        const float* k0 = &ks[j0 * 36];
        const float* k1 = k0 + 36;
#pragma unroll
        for (int d = 0; d < 32; d += 4) {
            float4 a0 = *(const float4*)(q0 + d);
            float4 a1 = *(const float4*)(q1 + d);
            float4 b0 = *(const float4*)(k0 + d);
            float4 b1 = *(const float4*)(k1 + d);
            s00 += a0.x * b0.x + a0.y * b0.y + a0.z * b0.z + a0.w * b0.w;
            s01 += a0.x * b1.x + a0.y * b1.y + a0.z * b1.z + a0.w * b1.w;
            s10 += a1.x * b0.x + a1.y * b0.y + a1.z * b0.z + a1.w * b0.w;
            s11 += a1.x * b1.x + a1.y * b1.y + a1.z * b1.z + a1.w * b1.w;
        }
        bool iv = (i0 + 1 < 49), jv = (j0 + 1 < 49);
        finish(i0, j0, s00);
        if (jv) finish(i0, j0 + 1, s01);
        if (iv) finish(i0 + 1, j0, s10);
        if (iv && jv) finish(i0 + 1, j0 + 1, s11);
    }
    __syncthreads();

    // softmax: warp per row
    {
        int warp = tid >> 5, lane = tid & 31;
        for (int r = warp; r < 49; r += 8) {
            float v0 = sc[r * 49 + lane];
            float v1 = (lane + 32 < 49) ? sc[r * 49 + lane + 32] : -1e30f;
            float mx = fmaxf(v0, v1);
#pragma unroll
            for (int o = 16; o > 0; o >>= 1) mx = fmaxf(mx, __shfl_xor_sync(0xffffffffu, mx, o));
            float e0 = __expf(v0 - mx);
            float e1 = (lane + 32 < 49) ? __expf(v1 - mx) : 0.f;
            float sum = e0 + e1;
#pragma unroll
            for (int o = 16; o > 0; o >>= 1) sum += __shfl_xor_sync(0xffffffffu, sum, o);
            float inv = 1.0f / sum;
            sc[r * 49 + lane] = e0 * inv;
            if (lane + 32 < 49) sc[r * 49 + lane + 32] = e1 * inv;
        }
    }
    __syncthreads();

    // O = P @ V : thread computes (row i, 4 dims), float4 V loads
    for (int t = tid; t < 49 * 8; t += 256) {
        int i = t >> 3, dq = (t & 7) * 4;
        const float* sr = &sc[i * 49];
        float4 acc = make_float4(0.f, 0.f, 0.f, 0.f);
#pragma unroll 7
        for (int j = 0; j < 49; j++) {
            float p = sr[j];
            float4 v = *(const float4*)&vs[j * 36 + dq];
            acc.x += p * v.x; acc.y += p * v.y; acc.z += p * v.z; acc.w += p * v.w;
        }
        float4 o;
        o.x = tf32r(acc.x); o.y = tf32r(acc.y); o.z = tf32r(acc.z); o.w = tf32r(acc.w);
        *(float4*)&out[(size_t)(wb * 49 + i) * 256 + h * 32 + dq] = o;
    }
}

// ---------------- launch ----------------
extern "C" void kernel_launch(void* const* d_in, const int* in_sizes, int n_in,
                              void* d_out, int out_size)
{
    const float* x      = (const float*)d_in[0];
    const float* gamma1 = (const float*)d_in[1];
    const float* beta1  = (const float*)d_in[2];
    const float* qkv_w  = (const float*)d_in[3];
    const float* qkv_b  = (const float*)d_in[4];
    const float* proj_w = (const float*)d_in[5];
    const float* proj_b = (const float*)d_in[6];
    const float* rpb    = (const float*)d_in[7];
    const float* gamma2 = (const float*)d_in[8];
    const float* beta2  = (const float*)d_in[9];
    const float* fc1_w  = (const float*)d_in[10];
    const float* fc1_b  = (const float*)d_in[11];
    const float* fc2_w  = (const float*)d_in[12];
    const float* fc2_b  = (const float*)d_in[13];
    float* out = (float*)d_out;

    float *pa, *pqkv, *ph, *pw;
    cudaGetSymbolAddress((void**)&pa, g_a);
    cudaGetSymbolAddress((void**)&pqkv, g_qkv);
    cudaGetSymbolAddress((void**)&ph, g_h);
    cudaGetSymbolAddress((void**)&pw, g_wT);

    const int DSMEM = 65536;   // 2 stages x (16KB A + 16KB B)
    cudaFuncSetAttribute(mma_gemm<256, 768, 0>, cudaFuncAttributeMaxDynamicSharedMemorySize, DSMEM);
    cudaFuncSetAttribute(mma_gemm<256, 256, 1>, cudaFuncAttributeMaxDynamicSharedMemorySize, DSMEM);
    cudaFuncSetAttribute(mma_gemm<256, 1024, 2>, cudaFuncAttributeMaxDynamicSharedMemorySize, DSMEM);
    cudaFuncSetAttribute(mma_gemm<1024, 256, 3>, cudaFuncAttributeMaxDynamicSharedMemorySize, DSMEM);

    // 0. transpose + tf32-round weights
    transpose_tf32<<<dim3(768 / 32, 256 / 32), dim3(32, 8)>>>(qkv_w, pw + OFF_QKVT, 256, 768);
    transpose_tf32<<<dim3(256 / 32, 256 / 32), dim3(32, 8)>>>(proj_w, pw + OFF_PROJT, 256, 256);
    transpose_tf32<<<dim3(1024 / 32, 256 / 32), dim3(32, 8)>>>(fc1_w, pw + OFF_FC1T, 256, 1024);
    transpose_tf32<<<dim3(256 / 32, 1024 / 32), dim3(32, 8)>>>(fc2_w, pw + OFF_FC2T, 1024, 256);

    // 1. LN1 + cyclic shift + window partition -> g_a
    ln_kernel<true><<<TOK / 8, 256>>>(x, gamma1, beta1, pa);
    // 2. QKV GEMM -> g_qkv
    mma_gemm<256, 768, 0><<<dim3(6, 784), 128, DSMEM>>>(pa, pw + OFF_QKVT, qkv_b, pqkv, nullptr);
    // 3. attention -> g_a (reused)
    attn_kernel<<<dim3(2048, 8), 256>>>(pqkv, rpb, pa);
    // 4. proj GEMM + window reverse + roll scatter + residual -> d_out
    mma_gemm<256, 256, 1><<<dim3(2, 784), 128, DSMEM>>>(pa, pw + OFF_PROJT, proj_b, out, x);
    // 5. LN2 -> g_qkv (reused)
    ln_kernel<false><<<TOK / 8, 256>>>(out, gamma2, beta2, pqkv);
    // 6. FC1 + GELU -> g_h
    mma_gemm<256, 1024, 2><<<dim3(8, 784), 128, DSMEM>>>(pqkv, pw + OFF_FC1T, fc1_b, ph, nullptr);
    // 7. FC2 + residual -> d_out
    mma_gemm<1024, 256, 3><<<dim3(2, 784), 128, DSMEM>>>(ph, pw + OFF_FC2T, fc2_b, out, out);
    (void)in_sizes; (void)n_in; (void)out_size;
}

// round 10
// speedup vs baseline: 3.3346x; 1.4572x over previous
#include <cuda_runtime.h>
#include <cuda_fp16.h>
#include <math.h>
#include <stdint.h>

// ---------------- static config ----------------
#define TOK   100352          // 32 * 56 * 56 tokens
#define SCALE 0.17677669529663687f   // 32^-0.5

// ---------------- scratch (device globals; no allocs allowed) ----------------
__device__ __half g_a[TOK * 256];     // LN1-window output; reused: attention out, LN2 out
__device__ __half g_qkv[TOK * 768];   // QKV output
__device__ __half g_h[TOK * 1024];    // FC1/GELU output
// transposed half weights: qkvT[768][256], projT[256][256], fc1T[1024][256], fc2T[256][1024]
__device__ __half g_wT[196608 + 65536 + 262144 + 262144];
#define OFF_QKVT 0
#define OFF_PROJT 196608
#define OFF_FC1T 262144
#define OFF_FC2T 524288

// ---------------- helpers ----------------
__device__ __forceinline__ float gelu_exact(float x)
{
    return 0.5f * x * (1.0f + erff(x * 0.70710678118654752f));
}

// unshifted destination row for window-layout row mr (window reverse + roll)
__device__ __forceinline__ int unshift_row(int mr)
{
    int ntok = mr % 49; int wb = mr / 49;
    int wwi = wb & 7, wh = (wb >> 3) & 7, b = wb >> 6;
    int r = ntok / 7, c = ntok % 7;
    int oh = wh * 7 + r + 3; if (oh >= 56) oh -= 56;
    int ow = wwi * 7 + c + 3; if (ow >= 56) ow -= 56;
    return b * 3136 + oh * 56 + ow;
}

__device__ __forceinline__ void cpa16(uint32_t dst, const void* src)
{
    asm volatile("cp.async.cg.shared.global [%0], [%1], 16;" :: "r"(dst), "l"(src));
}

__device__ __forceinline__ void ldsm4(uint32_t addr, uint32_t& r0, uint32_t& r1,
                                      uint32_t& r2, uint32_t& r3)
{
    asm volatile("ldmatrix.sync.aligned.m8n8.x4.shared.b16 {%0,%1,%2,%3}, [%4];"
                 : "=r"(r0), "=r"(r1), "=r"(r2), "=r"(r3) : "r"(addr));
}

// ---------------- merged weight transpose: 4 matrices in one launch ----------------
// in[K][N] -> out[N][K] (half). 32x32 tiles; block (32,8).
__device__ __forceinline__ void tr_tile(const float* __restrict__ in, __half* __restrict__ out,
                                        int K, int N, int t)
{
    __shared__ float tbuf[32][33];
    int nx = N / 32;
    int bx = (t % nx) * 32;   // n
    int by = (t / nx) * 32;   // k
    int tx = threadIdx.x, ty = threadIdx.y;
#pragma unroll
    for (int i = 0; i < 32; i += 8)
        tbuf[ty + i][tx] = in[(size_t)(by + ty + i) * N + bx + tx];
    __syncthreads();
#pragma unroll
    for (int i = 0; i < 32; i += 8)
        out[(size_t)(bx + ty + i) * K + by + tx] = __float2half_rn(tbuf[tx][ty + i]);
}

__global__ void transpose_all(const float* __restrict__ qkv_w, const float* __restrict__ proj_w,
                              const float* __restrict__ fc1_w, const float* __restrict__ fc2_w,
                              __half* __restrict__ wT)
{
    int b = blockIdx.x;
    if (b < 192)        tr_tile(qkv_w,  wT + OFF_QKVT, 256, 768,  b);
    else if (b < 256)   tr_tile(proj_w, wT + OFF_PROJT, 256, 256, b - 192);
    else if (b < 512)   tr_tile(fc1_w,  wT + OFF_FC1T, 256, 1024, b - 256);
    else                tr_tile(fc2_w,  wT + OFF_FC2T, 1024, 256, b - 512);
}

// ---------------- LayerNorm (optionally fused with shift+window gather), half out ----------
template<bool WIN>
__global__ void ln_kernel(const float* __restrict__ in, const float* __restrict__ gm,
                          const float* __restrict__ bt, __half* __restrict__ out)
{
    int gw   = (blockIdx.x * blockDim.x + threadIdx.x) >> 5;
    int lane = threadIdx.x & 31;
    if (gw >= TOK) return;

    const float* src;
    if (WIN) src = in + (size_t)unshift_row(gw) * 256;
    else     src = in + (size_t)gw * 256;

    float v[8];
#pragma unroll
    for (int i = 0; i < 8; i++) v[i] = src[lane + 32 * i];

    float s = 0.f;
#pragma unroll
    for (int i = 0; i < 8; i++) s += v[i];
#pragma unroll
    for (int o = 16; o > 0; o >>= 1) s += __shfl_xor_sync(0xffffffffu, s, o);
    float mean = s * (1.0f / 256.0f);

    float q = 0.f;
#pragma unroll
    for (int i = 0; i < 8; i++) { float d = v[i] - mean; q += d * d; }
#pragma unroll
    for (int o = 16; o > 0; o >>= 1) q += __shfl_xor_sync(0xffffffffu, q, o);
    float rstd = rsqrtf(q * (1.0f / 256.0f) + 1e-5f);

    __half* orow = out + (size_t)gw * 256;
#pragma unroll
    for (int i = 0; i < 8; i++) {
        int cc = lane + 32 * i;
        orow[cc] = __float2half_rn((v[i] - mean) * rstd * gm[cc] + bt[cc]);
    }
}

// ---------------- fp16 tensor-core GEMM (R4 structure, m16n8k16) ----------------
// C[M,NN] = A[M,K] @ BT^T + epilogue   (A, BT half; BT is [NN][K]; K in elements)
// MODE 0: out = half(acc + bias)                            (QKV)
// MODE 1: out[dst] = res[dst] + acc + bias, dst = unshift   (proj + scatter + residual, f32)
// MODE 2: out = half(gelu(acc + bias))                      (FC1)
// MODE 3: out = res + acc + bias                            (FC2 + residual, f32)
//
// block 128x128, BK=64 halves (128B rows), 4 warps (2x2), warp tile 64x64,
// smem 2 stages x (A 16KB + B 16KB) = 64KB, XOR swizzle identical to R4,
// cp.async staging, ldmatrix.x4 fragments with (lane&15, lane>>4) addressing.
template<int K, int NN, int MODE, typename OutT>
__global__ __launch_bounds__(128) void hgemm(
    const __half* __restrict__ A, const __half* __restrict__ BT,
    const float* __restrict__ bias, OutT* __restrict__ out,
    const float* __restrict__ res)
{
    extern __shared__ float smdyn[];
    const int tid  = threadIdx.x;
    const int lane = tid & 31;
    const int warp = tid >> 5;
    const int wm = warp >> 1, wn = warp & 1;
    const int bm = blockIdx.y, bn = blockIdx.x;

    const uint32_t sbase = (uint32_t)__cvta_generic_to_shared(smdyn);
    const uint32_t sA0 = sbase;            // 2 buffers x 16KB
    const uint32_t sB0 = sbase + 32768;    // 2 buffers x 16KB

    // staging: 16 rows x 8 granules (16B each = 8 halves), 8 row-steps of 16
    const int lr = tid >> 3;   // 0..15
    const int lg = tid & 7;    // 0..7
    const uint32_t swz = (uint32_t)((lg ^ (lr & 7)) << 4);
    const __half* Ag = A  + (size_t)(bm * 128 + lr) * K + lg * 8;
    const __half* Bg = BT + (size_t)(bn * 128 + lr) * K + lg * 8;
    const uint32_t dA = sA0 + lr * 128 + swz;
    const uint32_t dB = sB0 + lr * 128 + swz;

    float c[4][8][4];
#pragma unroll
    for (int i = 0; i < 4; i++)
#pragma unroll
        for (int j = 0; j < 8; j++)
#pragma unroll
            for (int l = 0; l < 4; l++) c[i][j][l] = 0.f;

#define PREF(KT_, BUF)                                                    \
    do {                                                                  \
        const __half* _a = Ag + (KT_) * 64;                               \
        const __half* _b = Bg + (KT_) * 64;                               \
        uint32_t _o = (BUF) * 16384;                                      \
        _Pragma("unroll")                                                 \
        for (int i = 0; i < 8; i++) {                                     \
            cpa16(dA + _o + i * 2048, _a + (size_t)i * 16 * K);           \
            cpa16(dB + _o + i * 2048, _b + (size_t)i * 16 * K);           \
        }                                                                 \
        asm volatile("cp.async.commit_group;");                           \
    } while (0)

    PREF(0, 0);
    asm volatile("cp.async.wait_group 0;");
    __syncthreads();

    // ldmatrix row bases (row&7 == lane&7 for all fragment rows)
    const int l15 = lane & 15, hi = lane >> 4, l7 = lane & 7;
    uint32_t aRow[4], bRow[4];
#pragma unroll
    for (int mi = 0; mi < 4; mi++) aRow[mi] = sA0 + (uint32_t)((wm * 64 + mi * 16 + l15) * 128);
#pragma unroll
    for (int j = 0; j < 4; j++)    bRow[j]  = sB0 + (uint32_t)((wn * 64 + j * 16 + l15) * 128);

    int buf = 0;
    const int KT = K / 64;
#pragma unroll 1
    for (int kt = 0; kt < KT; kt++) {
        if (kt + 1 < KT) PREF(kt + 1, buf ^ 1);
        const uint32_t boff = (uint32_t)(buf * 16384);
        // ks covers k16 per step: granules {2ks, 2ks+1} of this 128B row
#pragma unroll
        for (int ks = 0; ks < 4; ks++) {
            const uint32_t gph = (uint32_t)(((2 * ks + hi) ^ l7) << 4) + boff;
            uint32_t af[4][4], bq[4][4];
#pragma unroll
            for (int mi = 0; mi < 4; mi++)
                ldsm4(aRow[mi] + gph, af[mi][0], af[mi][1], af[mi][2], af[mi][3]);
#pragma unroll
            for (int j = 0; j < 4; j++)
                ldsm4(bRow[j] + gph, bq[j][0], bq[j][1], bq[j][2], bq[j][3]);
#pragma unroll
            for (int mi = 0; mi < 4; mi++)
#pragma unroll
                for (int ni = 0; ni < 8; ni++) {
                    asm volatile(
                        "mma.sync.aligned.m16n8k16.row.col.f32.f16.f16.f32 "
                        "{%0,%1,%2,%3}, {%4,%5,%6,%7}, {%8,%9}, {%0,%1,%2,%3};"
                        : "+f"(c[mi][ni][0]), "+f"(c[mi][ni][1]),
                          "+f"(c[mi][ni][2]), "+f"(c[mi][ni][3])
                        : "r"(af[mi][0]), "r"(af[mi][1]),
                          "r"(af[mi][2]), "r"(af[mi][3]),
                          "r"(bq[ni >> 1][ni & 1]), "r"(bq[ni >> 1][2 + (ni & 1)]));
                }
        }
        if (kt + 1 < KT) {
            asm volatile("cp.async.wait_group 0;");
            __syncthreads();
            buf ^= 1;
        }
    }
#undef PREF

    // ---- epilogue (C fragment: rows lane>>2 / +8, cols 2*(lane&3), +1) ----
#pragma unroll
    for (int mi = 0; mi < 4; mi++) {
        int mr0 = bm * 128 + wm * 64 + mi * 16 + (lane >> 2);
        int mr1 = mr0 + 8;
        size_t dst0, dst1;
        if (MODE == 1) { dst0 = (size_t)unshift_row(mr0); dst1 = (size_t)unshift_row(mr1); }
        else           { dst0 = (size_t)mr0;              dst1 = (size_t)mr1; }
#pragma unroll
        for (int ni = 0; ni < 8; ni++) {
            int col = bn * 128 + wn * 64 + ni * 8 + 2 * (lane & 3);
            float2 bb = *(const float2*)&bias[col];
            float2 o0, o1;
            o0.x = c[mi][ni][0] + bb.x; o0.y = c[mi][ni][1] + bb.y;
            o1.x = c[mi][ni][2] + bb.x; o1.y = c[mi][ni][3] + bb.y;
            if (MODE == 1 || MODE == 3) {
                float2 r0v = *(const float2*)&res[dst0 * NN + col];
                float2 r1v = *(const float2*)&res[dst1 * NN + col];
                o0.x += r0v.x; o0.y += r0v.y;
                o1.x += r1v.x; o1.y += r1v.y;
            }
            if (MODE == 2) {
                o0.x = gelu_exact(o0.x); o0.y = gelu_exact(o0.y);
                o1.x = gelu_exact(o1.x); o1.y = gelu_exact(o1.y);
            }
            if (MODE == 0 || MODE == 2) {
                *(__half2*)((__half*)out + dst0 * NN + col) = __floats2half2_rn(o0.x, o0.y);
                *(__half2*)((__half*)out + dst1 * NN + col) = __floats2half2_rn(o1.x, o1.y);
            } else {
                *(float2*)((float*)out + dst0 * NN + col) = o0;
                *(float2*)((float*)out + dst1 * NN + col) = o1;
            }
        }
    }
}

// ---------------- windowed attention (register-blocked, R9 version; half I/O) ----------
__global__ __launch_bounds__(256) void attn_kernel(const __half* __restrict__ qkv,
                                                   const float* __restrict__ rpb,
                                                   __half* __restrict__ out)
{
    const int wb = blockIdx.x;   // 0..2047
    const int h  = blockIdx.y;   // 0..7
    const int tid = threadIdx.x;

    __shared__ float qs[50 * 36];   // stride 36 (float4-aligned), padded row 49
    __shared__ float ks[50 * 36];
    __shared__ float vs[49 * 36];
    __shared__ float sc[49 * 49];
    __shared__ float rpb_s[169];
    __shared__ int   lab[49];

    for (int idx = tid; idx < 49 * 32; idx += 256) {
        int n = idx >> 5, d = idx & 31;
        size_t base = (size_t)(wb * 49 + n) * 768 + h * 32 + d;
        qs[n * 36 + d] = __half2float(qkv[base]) * SCALE;
        ks[n * 36 + d] = __half2float(qkv[base + 256]);
        vs[n * 36 + d] = __half2float(qkv[base + 512]);
    }
    if (tid < 32) { qs[49 * 36 + tid] = 0.f; ks[49 * 36 + tid] = 0.f; }  // pad row
    for (int i = tid; i < 169; i += 256) rpb_s[i] = rpb[i * 8 + h];
    if (tid < 49) {
        int wwi = wb & 7, wh = (wb >> 3) & 7;
        int r = tid / 7, c = tid % 7;
        int gr = wh * 7 + r, gc = wwi * 7 + c;
        int lr = gr < 49 ? 0 : (gr < 53 ? 1 : 2);
        int lc = gc < 49 ? 0 : (gc < 53 ? 1 : 2);
        lab[tid] = lr * 3 + lc;
    }
    __syncthreads();

    // scores: 2x2 register tiles over a 25x25 tile grid
    auto finish = [&](int i, int j, float s) {
        int ri = i / 7, ci = i % 7, rj = j / 7, cj = j % 7;
        s += rpb_s[(ri - rj + 6) * 13 + (ci - cj + 6)];
        if (lab[i] != lab[j]) s -= 100.0f;
        sc[i * 49 + j] = s;
    };
    for (int t = tid; t < 625; t += 256) {
        int ti = t / 25, tj = t % 25;
        int i0 = ti * 2, j0 = tj * 2;
        float s00 = 0.f, s01 = 0.f, s10 = 0.f, s11 = 0.f;
        const float* q0 = &qs[i0 * 36];
        const float* q1 = q0 + 36;
        const float* k0 = &ks[j0 * 36];
        const float* k1 = k0 + 36;
#pragma unroll
        for (int d = 0; d < 32; d += 4) {
            float4 a0 = *(const float4*)(q0 + d);
            float4 a1 = *(const float4*)(q1 + d);
            float4 b0 = *(const float4*)(k0 + d);
            float4 b1 = *(const float4*)(k1 + d);
            s00 += a0.x * b0.x + a0.y * b0.y + a0.z * b0.z + a0.w * b0.w;
            s01 += a0.x * b1.x + a0.y * b1.y + a0.z * b1.z + a0.w * b1.w;
            s10 += a1.x * b0.x + a1.y * b0.y + a1.z * b0.z + a1.w * b0.w;
            s11 += a1.x * b1.x + a1.y * b1.y + a1.z * b1.z + a1.w * b1.w;
        }
        bool iv = (i0 + 1 < 49), jv = (j0 + 1 < 49);
        finish(i0, j0, s00);
        if (jv) finish(i0, j0 + 1, s01);
        if (iv) finish(i0 + 1, j0, s10);
        if (iv && jv) finish(i0 + 1, j0 + 1, s11);
    }
    __syncthreads();

    // softmax: warp per row
    {
        int warp = tid >> 5, lane = tid & 31;
        for (int r = warp; r < 49; r += 8) {
            float v0 = sc[r * 49 + lane];
            float v1 = (lane + 32 < 49) ? sc[r * 49 + lane + 32] : -1e30f;
            float mx = fmaxf(v0, v1);
#pragma unroll
            for (int o = 16; o > 0; o >>= 1) mx = fmaxf(mx, __shfl_xor_sync(0xffffffffu, mx, o));
            float e0 = __expf(v0 - mx);
            float e1 = (lane + 32 < 49) ? __expf(v1 - mx) : 0.f;
            float sum = e0 + e1;
#pragma unroll
            for (int o = 16; o > 0; o >>= 1) sum += __shfl_xor_sync(0xffffffffu, sum, o);
            float inv = 1.0f / sum;
            sc[r * 49 + lane] = e0 * inv;
            if (lane + 32 < 49) sc[r * 49 + lane + 32] = e1 * inv;
        }
    }
    __syncthreads();

    // O = P @ V : thread computes (row i, 4 dims), half2-pair output
    for (int t = tid; t < 49 * 8; t += 256) {
        int i = t >> 3, dq = (t & 7) * 4;
        const float* sr = &sc[i * 49];
        float4 acc = make_float4(0.f, 0.f, 0.f, 0.f);
#pragma unroll 7
        for (int j = 0; j < 49; j++) {
            float p = sr[j];
            float4 v = *(const float4*)&vs[j * 36 + dq];
            acc.x += p * v.x; acc.y += p * v.y; acc.z += p * v.z; acc.w += p * v.w;
        }
        __half2 h01 = __floats2half2_rn(acc.x, acc.y);
        __half2 h23 = __floats2half2_rn(acc.z, acc.w);
        uint2 pk = make_uint2(*(uint32_t*)&h01, *(uint32_t*)&h23);
        *(uint2*)&out[(size_t)(wb * 49 + i) * 256 + h * 32 + dq] = pk;
    }
}

// ---------------- launch ----------------
extern "C" void kernel_launch(void* const* d_in, const int* in_sizes, int n_in,
                              void* d_out, int out_size)
{
    const float* x      = (const float*)d_in[0];
    const float* gamma1 = (const float*)d_in[1];
    const float* beta1  = (const float*)d_in[2];
    const float* qkv_w  = (const float*)d_in[3];
    const float* qkv_b  = (const float*)d_in[4];
    const float* proj_w = (const float*)d_in[5];
    const float* proj_b = (const float*)d_in[6];
    const float* rpb    = (const float*)d_in[7];
    const float* gamma2 = (const float*)d_in[8];
    const float* beta2  = (const float*)d_in[9];
    const float* fc1_w  = (const float*)d_in[10];
    const float* fc1_b  = (const float*)d_in[11];
    const float* fc2_w  = (const float*)d_in[12];
    const float* fc2_b  = (const float*)d_in[13];
    float* out = (float*)d_out;

    __half *pa, *pqkv, *ph, *pw;
    cudaGetSymbolAddress((void**)&pa, g_a);
    cudaGetSymbolAddress((void**)&pqkv, g_qkv);
    cudaGetSymbolAddress((void**)&ph, g_h);
    cudaGetSymbolAddress((void**)&pw, g_wT);

    const int DSMEM = 65536;   // 2 stages x (16KB A + 16KB B)
    cudaFuncSetAttribute(hgemm<256, 768, 0, __half>,  cudaFuncAttributeMaxDynamicSharedMemorySize, DSMEM);
    cudaFuncSetAttribute(hgemm<256, 256, 1, float>,   cudaFuncAttributeMaxDynamicSharedMemorySize, DSMEM);
    cudaFuncSetAttribute(hgemm<256, 1024, 2, __half>, cudaFuncAttributeMaxDynamicSharedMemorySize, DSMEM);
    cudaFuncSetAttribute(hgemm<1024, 256, 3, float>,  cudaFuncAttributeMaxDynamicSharedMemorySize, DSMEM);

    // 0. transpose + half-round all weights (single launch)
    transpose_all<<<768, dim3(32, 8)>>>(qkv_w, proj_w, fc1_w, fc2_w, pw);

    // 1. LN1 + cyclic shift + window partition -> g_a (half)
    ln_kernel<true><<<TOK / 8, 256>>>(x, gamma1, beta1, pa);
    // 2. QKV GEMM -> g_qkv (half)
    hgemm<256, 768, 0, __half><<<dim3(6, 784), 128, DSMEM>>>(pa, pw + OFF_QKVT, qkv_b, pqkv, nullptr);
    // 3. attention -> g_a (reused, half)
    attn_kernel<<<dim3(2048, 8), 256>>>(pqkv, rpb, pa);
    // 4. proj GEMM + window reverse + roll scatter + residual -> d_out (f32)
    hgemm<256, 256, 1, float><<<dim3(2, 784), 128, DSMEM>>>(pa, pw + OFF_PROJT, proj_b, out, x);
    // 5. LN2 -> g_a (reused, half)
    ln_kernel<false><<<TOK / 8, 256>>>(out, gamma2, beta2, pa);
    // 6. FC1 + GELU -> g_h (half)
    hgemm<256, 1024, 2, __half><<<dim3(8, 784), 128, DSMEM>>>(pa, pw + OFF_FC1T, fc1_b, ph, nullptr);
    // 7. FC2 + residual -> d_out (f32)
    hgemm<1024, 256, 3, float><<<dim3(2, 784), 128, DSMEM>>>(ph, pw + OFF_FC2T, fc2_b, out, out);
    (void)in_sizes; (void)n_in; (void)out_size;
}

// round 11
// speedup vs baseline: 4.9240x; 1.4766x over previous
#include <cuda_runtime.h>
#include <cuda_fp16.h>
#include <math.h>
#include <stdint.h>

// ---------------- static config ----------------
#define TOK   100352          // 32 * 56 * 56 tokens
#define SCALE 0.17677669529663687f   // 32^-0.5

// ---------------- scratch (device globals; no allocs allowed) ----------------
__device__ __half g_a[TOK * 256];     // LN1-window output; reused: attention out, LN2 out
__device__ __half g_qkv[TOK * 768];   // QKV output
__device__ __half g_h[TOK * 1024];    // FC1/GELU output
// transposed half weights
__device__ __half g_wT[196608 + 65536 + 262144 + 262144];
#define OFF_QKVT 0
#define OFF_PROJT 196608
#define OFF_FC1T 262144
#define OFF_FC2T 524288

// ---------------- helpers ----------------
__device__ __forceinline__ float gelu_exact(float x)
{
    return 0.5f * x * (1.0f + erff(x * 0.70710678118654752f));
}

__device__ __forceinline__ int unshift_row(int mr)
{
    int ntok = mr % 49; int wb = mr / 49;
    int wwi = wb & 7, wh = (wb >> 3) & 7, b = wb >> 6;
    int r = ntok / 7, c = ntok % 7;
    int oh = wh * 7 + r + 3; if (oh >= 56) oh -= 56;
    int ow = wwi * 7 + c + 3; if (ow >= 56) ow -= 56;
    return b * 3136 + oh * 56 + ow;
}

__device__ __forceinline__ void cpa16(uint32_t dst, const void* src)
{
    asm volatile("cp.async.cg.shared.global [%0], [%1], 16;" :: "r"(dst), "l"(src));
}

__device__ __forceinline__ void ldsm4(uint32_t addr, uint32_t& r0, uint32_t& r1,
                                      uint32_t& r2, uint32_t& r3)
{
    asm volatile("ldmatrix.sync.aligned.m8n8.x4.shared.b16 {%0,%1,%2,%3}, [%4];"
                 : "=r"(r0), "=r"(r1), "=r"(r2), "=r"(r3) : "r"(addr));
}

__device__ __forceinline__ void ldsm4t(uint32_t addr, uint32_t& r0, uint32_t& r1,
                                       uint32_t& r2, uint32_t& r3)
{
    asm volatile("ldmatrix.sync.aligned.m8n8.x4.trans.shared.b16 {%0,%1,%2,%3}, [%4];"
                 : "=r"(r0), "=r"(r1), "=r"(r2), "=r"(r3) : "r"(addr));
}

__device__ __forceinline__ uint32_t packh2(float a, float b)
{
    __half2 h = __floats2half2_rn(a, b);
    return *(uint32_t*)&h;
}

#define MMA16816(C, A0, A1, A2, A3, B0, B1)                                 \
    asm volatile(                                                           \
        "mma.sync.aligned.m16n8k16.row.col.f32.f16.f16.f32 "                \
        "{%0,%1,%2,%3}, {%4,%5,%6,%7}, {%8,%9}, {%0,%1,%2,%3};"             \
        : "+f"((C)[0]), "+f"((C)[1]), "+f"((C)[2]), "+f"((C)[3])            \
        : "r"(A0), "r"(A1), "r"(A2), "r"(A3), "r"(B0), "r"(B1))

// ---------------- merged weight transpose ----------------
__device__ __forceinline__ void tr_tile(const float* __restrict__ in, __half* __restrict__ out,
                                        int K, int N, int t)
{
    __shared__ float tbuf[32][33];
    int nx = N / 32;
    int bx = (t % nx) * 32;
    int by = (t / nx) * 32;
    int tx = threadIdx.x, ty = threadIdx.y;
#pragma unroll
    for (int i = 0; i < 32; i += 8)
        tbuf[ty + i][tx] = in[(size_t)(by + ty + i) * N + bx + tx];
    __syncthreads();
#pragma unroll
    for (int i = 0; i < 32; i += 8)
        out[(size_t)(bx + ty + i) * K + by + tx] = __float2half_rn(tbuf[tx][ty + i]);
}

__global__ void transpose_all(const float* __restrict__ qkv_w, const float* __restrict__ proj_w,
                              const float* __restrict__ fc1_w, const float* __restrict__ fc2_w,
                              __half* __restrict__ wT)
{
    int b = blockIdx.x;
    if (b < 192)        tr_tile(qkv_w,  wT + OFF_QKVT, 256, 768,  b);
    else if (b < 256)   tr_tile(proj_w, wT + OFF_PROJT, 256, 256, b - 192);
    else if (b < 512)   tr_tile(fc1_w,  wT + OFF_FC1T, 256, 1024, b - 256);
    else                tr_tile(fc2_w,  wT + OFF_FC2T, 1024, 256, b - 512);
}

// ---------------- LayerNorm (optionally fused shift+window gather), half out ----------
template<bool WIN>
__global__ void ln_kernel(const float* __restrict__ in, const float* __restrict__ gm,
                          const float* __restrict__ bt, __half* __restrict__ out)
{
    int gw   = (blockIdx.x * blockDim.x + threadIdx.x) >> 5;
    int lane = threadIdx.x & 31;
    if (gw >= TOK) return;

    const float* src;
    if (WIN) src = in + (size_t)unshift_row(gw) * 256;
    else     src = in + (size_t)gw * 256;

    float v[8];
#pragma unroll
    for (int i = 0; i < 8; i++) v[i] = src[lane + 32 * i];

    float s = 0.f;
#pragma unroll
    for (int i = 0; i < 8; i++) s += v[i];
#pragma unroll
    for (int o = 16; o > 0; o >>= 1) s += __shfl_xor_sync(0xffffffffu, s, o);
    float mean = s * (1.0f / 256.0f);

    float q = 0.f;
#pragma unroll
    for (int i = 0; i < 8; i++) { float d = v[i] - mean; q += d * d; }
#pragma unroll
    for (int o = 16; o > 0; o >>= 1) q += __shfl_xor_sync(0xffffffffu, q, o);
    float rstd = rsqrtf(q * (1.0f / 256.0f) + 1e-5f);

    __half* orow = out + (size_t)gw * 256;
#pragma unroll
    for (int i = 0; i < 8; i++) {
        int cc = lane + 32 * i;
        orow[cc] = __float2half_rn((v[i] - mean) * rstd * gm[cc] + bt[cc]);
    }
}

// ---------------- fp16 tensor-core GEMM (R10, unchanged) ----------------
template<int K, int NN, int MODE, typename OutT>
__global__ __launch_bounds__(128) void hgemm(
    const __half* __restrict__ A, const __half* __restrict__ BT,
    const float* __restrict__ bias, OutT* __restrict__ out,
    const float* __restrict__ res)
{
    extern __shared__ float smdyn[];
    const int tid  = threadIdx.x;
    const int lane = tid & 31;
    const int warp = tid >> 5;
    const int wm = warp >> 1, wn = warp & 1;
    const int bm = blockIdx.y, bn = blockIdx.x;

    const uint32_t sbase = (uint32_t)__cvta_generic_to_shared(smdyn);
    const uint32_t sA0 = sbase;
    const uint32_t sB0 = sbase + 32768;

    const int lr = tid >> 3;
    const int lg = tid & 7;
    const uint32_t swz = (uint32_t)((lg ^ (lr & 7)) << 4);
    const __half* Ag = A  + (size_t)(bm * 128 + lr) * K + lg * 8;
    const __half* Bg = BT + (size_t)(bn * 128 + lr) * K + lg * 8;
    const uint32_t dA = sA0 + lr * 128 + swz;
    const uint32_t dB = sB0 + lr * 128 + swz;

    float c[4][8][4];
#pragma unroll
    for (int i = 0; i < 4; i++)
#pragma unroll
        for (int j = 0; j < 8; j++)
#pragma unroll
            for (int l = 0; l < 4; l++) c[i][j][l] = 0.f;

#define PREF(KT_, BUF)                                                    \
    do {                                                                  \
        const __half* _a = Ag + (KT_) * 64;                               \
        const __half* _b = Bg + (KT_) * 64;                               \
        uint32_t _o = (BUF) * 16384;                                      \
        _Pragma("unroll")                                                 \
        for (int i = 0; i < 8; i++) {                                     \
            cpa16(dA + _o + i * 2048, _a + (size_t)i * 16 * K);           \
            cpa16(dB + _o + i * 2048, _b + (size_t)i * 16 * K);           \
        }                                                                 \
        asm volatile("cp.async.commit_group;");                           \
    } while (0)

    PREF(0, 0);
    asm volatile("cp.async.wait_group 0;");
    __syncthreads();

    const int l15 = lane & 15, hi = lane >> 4, l7 = lane & 7;
    uint32_t aRow[4], bRow[4];
#pragma unroll
    for (int mi = 0; mi < 4; mi++) aRow[mi] = sA0 + (uint32_t)((wm * 64 + mi * 16 + l15) * 128);
#pragma unroll
    for (int j = 0; j < 4; j++)    bRow[j]  = sB0 + (uint32_t)((wn * 64 + j * 16 + l15) * 128);

    int buf = 0;
    const int KT = K / 64;
#pragma unroll 1
    for (int kt = 0; kt < KT; kt++) {
        if (kt + 1 < KT) PREF(kt + 1, buf ^ 1);
        const uint32_t boff = (uint32_t)(buf * 16384);
#pragma unroll
        for (int ks = 0; ks < 4; ks++) {
            const uint32_t gph = (uint32_t)(((2 * ks + hi) ^ l7) << 4) + boff;
            uint32_t af[4][4], bq[4][4];
#pragma unroll
            for (int mi = 0; mi < 4; mi++)
                ldsm4(aRow[mi] + gph, af[mi][0], af[mi][1], af[mi][2], af[mi][3]);
#pragma unroll
            for (int j = 0; j < 4; j++)
                ldsm4(bRow[j] + gph, bq[j][0], bq[j][1], bq[j][2], bq[j][3]);
#pragma unroll
            for (int mi = 0; mi < 4; mi++)
#pragma unroll
                for (int ni = 0; ni < 8; ni++)
                    MMA16816(c[mi][ni], af[mi][0], af[mi][1], af[mi][2], af[mi][3],
                             bq[ni >> 1][ni & 1], bq[ni >> 1][2 + (ni & 1)]);
        }
        if (kt + 1 < KT) {
            asm volatile("cp.async.wait_group 0;");
            __syncthreads();
            buf ^= 1;
        }
    }
#undef PREF

#pragma unroll
    for (int mi = 0; mi < 4; mi++) {
        int mr0 = bm * 128 + wm * 64 + mi * 16 + (lane >> 2);
        int mr1 = mr0 + 8;
        size_t dst0, dst1;
        if (MODE == 1) { dst0 = (size_t)unshift_row(mr0); dst1 = (size_t)unshift_row(mr1); }
        else           { dst0 = (size_t)mr0;              dst1 = (size_t)mr1; }
#pragma unroll
        for (int ni = 0; ni < 8; ni++) {
            int col = bn * 128 + wn * 64 + ni * 8 + 2 * (lane & 3);
            float2 bb = *(const float2*)&bias[col];
            float2 o0, o1;
            o0.x = c[mi][ni][0] + bb.x; o0.y = c[mi][ni][1] + bb.y;
            o1.x = c[mi][ni][2] + bb.x; o1.y = c[mi][ni][3] + bb.y;
            if (MODE == 1 || MODE == 3) {
                float2 r0v = *(const float2*)&res[dst0 * NN + col];
                float2 r1v = *(const float2*)&res[dst1 * NN + col];
                o0.x += r0v.x; o0.y += r0v.y;
                o1.x += r1v.x; o1.y += r1v.y;
            }
            if (MODE == 2) {
                o0.x = gelu_exact(o0.x); o0.y = gelu_exact(o0.y);
                o1.x = gelu_exact(o1.x); o1.y = gelu_exact(o1.y);
            }
            if (MODE == 0 || MODE == 2) {
                *(__half2*)((__half*)out + dst0 * NN + col) = __floats2half2_rn(o0.x, o0.y);
                *(__half2*)((__half*)out + dst1 * NN + col) = __floats2half2_rn(o1.x, o1.y);
            } else {
                *(float2*)((float*)out + dst0 * NN + col) = o0;
                *(float2*)((float*)out + dst1 * NN + col) = o1;
            }
        }
    }
}

// ---------------- tensor-core windowed attention ----------------
// block = one (window, head); 128 threads / 4 warps; warp w owns score rows w*16..w*16+15.
// Q/K/V staged 64x32 half, row stride 40 halves (80B) -> ldmatrix conflict-free (5r mod 8 perm).
__global__ __launch_bounds__(128) void attn_mma(const __half* __restrict__ qkv,
                                                const float* __restrict__ rpb,
                                                __half* __restrict__ out)
{
    const int wb = blockIdx.x;   // 0..2047
    const int h  = blockIdx.y;   // 0..7
    const int tid = threadIdx.x;
    const int lane = tid & 31;
    const int warp = tid >> 5;

    __shared__ __align__(16) __half sQ[64 * 40];
    __shared__ __align__(16) __half sK[64 * 40];
    __shared__ __align__(16) __half sV[64 * 40];
    __shared__ float rpb_s[169];
    __shared__ int meta[49];     // (lab<<8) | (r<<4) | c

    // stage Q,K,V (49 rows x 32 halves, 16B chunks)
    for (int idx = tid; idx < 49 * 4; idx += 128) {
        int n = idx >> 2, c8 = idx & 3;
        const __half* src = qkv + (size_t)(wb * 49 + n) * 768 + h * 32 + c8 * 8;
        *(uint4*)&sQ[n * 40 + c8 * 8] = *(const uint4*)src;
        *(uint4*)&sK[n * 40 + c8 * 8] = *(const uint4*)(src + 256);
        *(uint4*)&sV[n * 40 + c8 * 8] = *(const uint4*)(src + 512);
    }
    // zero pad rows 49..63
    for (int idx = tid; idx < 15 * 4; idx += 128) {
        int n = 49 + (idx >> 2), c8 = idx & 3;
        uint4 z = make_uint4(0, 0, 0, 0);
        *(uint4*)&sQ[n * 40 + c8 * 8] = z;
        *(uint4*)&sK[n * 40 + c8 * 8] = z;
        *(uint4*)&sV[n * 40 + c8 * 8] = z;
    }
    for (int i = tid; i < 169; i += 128) rpb_s[i] = rpb[i * 8 + h];
    if (tid < 49) {
        int wwi = wb & 7, wh = (wb >> 3) & 7;
        int r = tid / 7, c = tid % 7;
        int gr = wh * 7 + r, gc = wwi * 7 + c;
        int lr = gr < 49 ? 0 : (gr < 53 ? 1 : 2);
        int lc = gc < 49 ? 0 : (gc < 53 ? 1 : 2);
        meta[tid] = ((lr * 3 + lc) << 8) | (r << 4) | c;
    }
    __syncthreads();

    const uint32_t sQb = (uint32_t)__cvta_generic_to_shared(sQ);
    const uint32_t sKb = (uint32_t)__cvta_generic_to_shared(sK);
    const uint32_t sVb = (uint32_t)__cvta_generic_to_shared(sV);
    const int l15 = lane & 15, hi = lane >> 4;

    // ---- scores S[16x64] = Q_band @ K^T ----
    float c[8][4];
#pragma unroll
    for (int nt = 0; nt < 8; nt++)
#pragma unroll
        for (int q = 0; q < 4; q++) c[nt][q] = 0.f;

    {
        uint32_t aq[2][4];
#pragma unroll
        for (int kc = 0; kc < 2; kc++)
            ldsm4(sQb + (uint32_t)((warp * 16 + l15) * 80 + (kc * 2 + hi) * 16),
                  aq[kc][0], aq[kc][1], aq[kc][2], aq[kc][3]);
#pragma unroll
        for (int kc = 0; kc < 2; kc++) {
            uint32_t bk[4][4];
#pragma unroll
            for (int jt = 0; jt < 4; jt++)
                ldsm4(sKb + (uint32_t)((jt * 16 + l15) * 80 + (kc * 2 + hi) * 16),
                      bk[jt][0], bk[jt][1], bk[jt][2], bk[jt][3]);
#pragma unroll
            for (int nt = 0; nt < 8; nt++)
                MMA16816(c[nt], aq[kc][0], aq[kc][1], aq[kc][2], aq[kc][3],
                         bk[nt >> 1][nt & 1], bk[nt >> 1][2 + (nt & 1)]);
        }
    }

    // ---- scale + bias + mask in fragments ----
    const int iLo = warp * 16 + (lane >> 2);
    const int iHi = iLo + 8;
    const int mLo = (iLo < 49) ? meta[iLo] : 0;
    const int mHi = (iHi < 49) ? meta[iHi] : 0;
    const int riL = (mLo >> 4) & 15, ciL = mLo & 15, lbL = mLo >> 8;
    const int riH = (mHi >> 4) & 15, ciH = mHi & 15, lbH = mHi >> 8;

#pragma unroll
    for (int nt = 0; nt < 8; nt++) {
#pragma unroll
        for (int q = 0; q < 2; q++) {
            int j = nt * 8 + 2 * (lane & 3) + q;
            if (j < 49) {
                int mj = meta[j];
                int rj = (mj >> 4) & 15, cj = mj & 15, lbj = mj >> 8;
                float bL = rpb_s[(riL - rj + 6) * 13 + (ciL - cj + 6)];
                float bH = rpb_s[(riH - rj + 6) * 13 + (ciH - cj + 6)];
                float sL = c[nt][q] * SCALE + bL;
                float sH = c[nt][2 + q] * SCALE + bH;
                if (lbL != lbj) sL -= 100.f;
                if (lbH != lbj) sH -= 100.f;
                c[nt][q] = sL;
                c[nt][2 + q] = sH;
            } else {
                c[nt][q] = -10000.f;
                c[nt][2 + q] = -10000.f;
            }
        }
    }

    // ---- softmax per row (4 lanes per row: shfl xor 1,2) ----
    {
        float mxL = -1e30f, mxH = -1e30f;
#pragma unroll
        for (int nt = 0; nt < 8; nt++) {
            mxL = fmaxf(mxL, fmaxf(c[nt][0], c[nt][1]));
            mxH = fmaxf(mxH, fmaxf(c[nt][2], c[nt][3]));
        }
        mxL = fmaxf(mxL, __shfl_xor_sync(0xffffffffu, mxL, 1));
        mxL = fmaxf(mxL, __shfl_xor_sync(0xffffffffu, mxL, 2));
        mxH = fmaxf(mxH, __shfl_xor_sync(0xffffffffu, mxH, 1));
        mxH = fmaxf(mxH, __shfl_xor_sync(0xffffffffu, mxH, 2));
        float smL = 0.f, smH = 0.f;
#pragma unroll
        for (int nt = 0; nt < 8; nt++) {
            c[nt][0] = __expf(c[nt][0] - mxL); smL += c[nt][0];
            c[nt][1] = __expf(c[nt][1] - mxL); smL += c[nt][1];
            c[nt][2] = __expf(c[nt][2] - mxH); smH += c[nt][2];
            c[nt][3] = __expf(c[nt][3] - mxH); smH += c[nt][3];
        }
        smL += __shfl_xor_sync(0xffffffffu, smL, 1);
        smL += __shfl_xor_sync(0xffffffffu, smL, 2);
        smH += __shfl_xor_sync(0xffffffffu, smH, 1);
        smH += __shfl_xor_sync(0xffffffffu, smH, 2);
        float ivL = 1.0f / smL, ivH = 1.0f / smH;
#pragma unroll
        for (int nt = 0; nt < 8; nt++) {
            c[nt][0] *= ivL; c[nt][1] *= ivL;
            c[nt][2] *= ivH; c[nt][3] *= ivH;
        }
    }

    // ---- O[16x32] = P @ V  (P fragments direct from registers; V via ldsm.trans) ----
    float o[4][4];
#pragma unroll
    for (int nt = 0; nt < 4; nt++)
#pragma unroll
        for (int q = 0; q < 4; q++) o[nt][q] = 0.f;

#pragma unroll
    for (int kc2 = 0; kc2 < 4; kc2++) {
        uint32_t ap0 = packh2(c[2 * kc2][0],     c[2 * kc2][1]);
        uint32_t ap1 = packh2(c[2 * kc2][2],     c[2 * kc2][3]);
        uint32_t ap2 = packh2(c[2 * kc2 + 1][0], c[2 * kc2 + 1][1]);
        uint32_t ap3 = packh2(c[2 * kc2 + 1][2], c[2 * kc2 + 1][3]);
        uint32_t bv[2][4];
#pragma unroll
        for (int dp = 0; dp < 2; dp++)
            ldsm4t(sVb + (uint32_t)((kc2 * 16 + l15) * 80 + (dp * 2 + hi) * 16),
                   bv[dp][0], bv[dp][1], bv[dp][2], bv[dp][3]);
#pragma unroll
        for (int nt = 0; nt < 4; nt++)
            MMA16816(o[nt], ap0, ap1, ap2, ap3,
                     bv[nt >> 1][2 * (nt & 1)], bv[nt >> 1][2 * (nt & 1) + 1]);
    }

    // ---- write O rows < 49 ----
#pragma unroll
    for (int nt = 0; nt < 4; nt++) {
        int col = h * 32 + nt * 8 + 2 * (lane & 3);
        if (iLo < 49)
            *(__half2*)&out[(size_t)(wb * 49 + iLo) * 256 + col] =
                __floats2half2_rn(o[nt][0], o[nt][1]);
        if (iHi < 49)
            *(__half2*)&out[(size_t)(wb * 49 + iHi) * 256 + col] =
                __floats2half2_rn(o[nt][2], o[nt][3]);
    }
}

// ---------------- launch ----------------
extern "C" void kernel_launch(void* const* d_in, const int* in_sizes, int n_in,
                              void* d_out, int out_size)
{
    const float* x      = (const float*)d_in[0];
    const float* gamma1 = (const float*)d_in[1];
    const float* beta1  = (const float*)d_in[2];
    const float* qkv_w  = (const float*)d_in[3];
    const float* qkv_b  = (const float*)d_in[4];
    const float* proj_w = (const float*)d_in[5];
    const float* proj_b = (const float*)d_in[6];
    const float* rpb    = (const float*)d_in[7];
    const float* gamma2 = (const float*)d_in[8];
    const float* beta2  = (const float*)d_in[9];
    const float* fc1_w  = (const float*)d_in[10];
    const float* fc1_b  = (const float*)d_in[11];
    const float* fc2_w  = (const float*)d_in[12];
    const float* fc2_b  = (const float*)d_in[13];
    float* out = (float*)d_out;

    __half *pa, *pqkv, *ph, *pw;
    cudaGetSymbolAddress((void**)&pa, g_a);
    cudaGetSymbolAddress((void**)&pqkv, g_qkv);
    cudaGetSymbolAddress((void**)&ph, g_h);
    cudaGetSymbolAddress((void**)&pw, g_wT);

    const int DSMEM = 65536;
    cudaFuncSetAttribute(hgemm<256, 768, 0, __half>,  cudaFuncAttributeMaxDynamicSharedMemorySize, DSMEM);
    cudaFuncSetAttribute(hgemm<256, 256, 1, float>,   cudaFuncAttributeMaxDynamicSharedMemorySize, DSMEM);
    cudaFuncSetAttribute(hgemm<256, 1024, 2, __half>, cudaFuncAttributeMaxDynamicSharedMemorySize, DSMEM);
    cudaFuncSetAttribute(hgemm<1024, 256, 3, float>,  cudaFuncAttributeMaxDynamicSharedMemorySize, DSMEM);

    // 0. transpose + half-round all weights (single launch)
    transpose_all<<<768, dim3(32, 8)>>>(qkv_w, proj_w, fc1_w, fc2_w, pw);

    // 1. LN1 + cyclic shift + window partition -> g_a (half)
    ln_kernel<true><<<TOK / 8, 256>>>(x, gamma1, beta1, pa);
    // 2. QKV GEMM -> g_qkv (half)
    hgemm<256, 768, 0, __half><<<dim3(6, 784), 128, DSMEM>>>(pa, pw + OFF_QKVT, qkv_b, pqkv, nullptr);
    // 3. tensor-core attention -> g_a (reused, half)
    attn_mma<<<dim3(2048, 8), 128>>>(pqkv, rpb, pa);
    // 4. proj GEMM + window reverse + roll scatter + residual -> d_out (f32)
    hgemm<256, 256, 1, float><<<dim3(2, 784), 128, DSMEM>>>(pa, pw + OFF_PROJT, proj_b, out, x);
    // 5. LN2 -> g_a (reused, half)
    ln_kernel<false><<<TOK / 8, 256>>>(out, gamma2, beta2, pa);
    // 6. FC1 + GELU -> g_h (half)
    hgemm<256, 1024, 2, __half><<<dim3(8, 784), 128, DSMEM>>>(pa, pw + OFF_FC1T, fc1_b, ph, nullptr);
    // 7. FC2 + residual -> d_out (f32)
    hgemm<1024, 256, 3, float><<<dim3(2, 784), 128, DSMEM>>>(ph, pw + OFF_FC2T, fc2_b, out, out);
    (void)in_sizes; (void)n_in; (void)out_size;
}